// round 3
// baseline (speedup 1.0000x reference)
#include <cuda_runtime.h>
#include <cuda_bf16.h>

// CompositeValueNoise, spatially-binned version.
// Pipeline: zero-hist -> histogram(18-bit cell key) -> exclusive scan ->
// scatter (sorted float4 {x,y,z,idx}) -> main 2-lanes-per-point kernel.
// Sorting makes a warp's 16 points spatially adjacent so corner-load
// instructions touch few distinct cache lines (R2 bottleneck: L1tex
// wavefronts, 88% of peak with zero inter-point merging).

#define N_FIELDS 4
#define MAXN 2000000
#define BBITS 6                      // bits per dim
#define BDIM (1 << BBITS)            // 64
#define NBUCK (BDIM * BDIM * BDIM)   // 262144

__device__ int    g_hist[NBUCK];
__device__ float4 g_sorted[MAXN];

__device__ __forceinline__ int cell_key(float px, float py, float pz) {
    int ci = min(max((int)(px * (float)BDIM), 0), BDIM - 1);
    int cj = min(max((int)(py * (float)BDIM), 0), BDIM - 1);
    int ck = min(max((int)(pz * (float)BDIM), 0), BDIM - 1);
    // k innermost: consecutive buckets are adjacent along the innermost
    // memory dimension of the grids -> best line sharing across buckets.
    return (ci << (2 * BBITS)) | (cj << BBITS) | ck;
}

__global__ void zero_hist_kernel() {
    int i = blockIdx.x * blockDim.x + threadIdx.x;
    if (i < NBUCK) g_hist[i] = 0;
}

__global__ void hist_kernel(const float* __restrict__ x, int n) {
    int i = blockIdx.x * blockDim.x + threadIdx.x;
    if (i >= n) return;
    float px = x[3 * i], py = x[3 * i + 1], pz = x[3 * i + 2];
    atomicAdd(&g_hist[cell_key(px, py, pz)], 1);
}

// Single-block exclusive scan over NBUCK counters (in place).
__global__ void scan_kernel() {
    __shared__ int sums[1024];
    const int tid = threadIdx.x;
    const int chunk = NBUCK / 1024;       // 256
    const int base = tid * chunk;

    int s = 0;
    for (int c = 0; c < chunk; ++c) s += g_hist[base + c];
    sums[tid] = s;
    __syncthreads();

    // inclusive Hillis-Steele scan over 1024 partials
    for (int off = 1; off < 1024; off <<= 1) {
        int v = (tid >= off) ? sums[tid - off] : 0;
        __syncthreads();
        sums[tid] += v;
        __syncthreads();
    }
    int run = sums[tid] - s;              // exclusive prefix of this chunk
    for (int c = 0; c < chunk; ++c) {
        int v = g_hist[base + c];
        g_hist[base + c] = run;
        run += v;
    }
}

__global__ void scatter_kernel(const float* __restrict__ x, int n) {
    int i = blockIdx.x * blockDim.x + threadIdx.x;
    if (i >= n) return;
    float px = x[3 * i], py = x[3 * i + 1], pz = x[3 * i + 2];
    int pos = atomicAdd(&g_hist[cell_key(px, py, pz)], 1);
    g_sorted[pos] = make_float4(px, py, pz, __int_as_float(i));
}

__device__ __forceinline__ float4 ld4(const float* __restrict__ p) {
    return __ldg(reinterpret_cast<const float4*>(p));
}

__device__ __forceinline__ float4 lerp4(float4 a, float4 b, float w) {
    float4 r;
    r.x = fmaf(w, b.x - a.x, a.x);
    r.y = fmaf(w, b.y - a.y, a.y);
    r.z = fmaf(w, b.z - a.z, a.z);
    r.w = fmaf(w, b.w - a.w, a.w);
    return r;
}

__global__ void __launch_bounds__(256) composite_value_noise_kernel(
    const float* __restrict__ V16,
    const float* __restrict__ V32,
    const float* __restrict__ V64,
    const float* __restrict__ V128,
    float* __restrict__ out,
    int n)
{
    int gtid = blockIdx.x * blockDim.x + threadIdx.x;
    int p  = gtid >> 1;       // sorted point slot
    int kk = gtid & 1;        // which k corner this lane owns
    if (p >= n) return;

    float4 pt = g_sorted[p];  // both lanes of the pair: same addr -> broadcast
    const float px = pt.x, py = pt.y, pz = pt.z;
    const int   idx = __float_as_int(pt.w);

    const float* grids[4] = {V16, V32, V64, V128};
    const int    ress[4]  = {16, 32, 64, 128};

    float4 acc = make_float4(0.f, 0.f, 0.f, 0.f);

    #pragma unroll
    for (int L = 0; L < 4; ++L) {
        const float* __restrict__ V = grids[L];
        const int   res  = ress[L];
        const float resf = (float)res;
        const float mult = 16.0f / resf;

        float xs = fmodf(px * resf, resf);
        float ys = fmodf(py * resf, resf);
        float zs = fmodf(pz * resf, resf);

        float fx = floorf(xs), fy = floorf(ys), fz = floorf(zs);
        float tx = xs - fx,    ty = ys - fy,    tz = zs - fz;

        int i0 = (int)fx, j0 = (int)fy, k0 = (int)fz;

        float wx = (3.0f - 2.0f * tx) * tx * tx;
        float wy = (3.0f - 2.0f * ty) * ty * ty;
        float wz = (3.0f - 2.0f * tz) * tz * tz;

        const int r1 = res + 1;
        const int s1 = r1 * N_FIELDS;   // dim-1 stride (floats)
        const int s0 = r1 * s1;         // dim-0 stride (floats)

        const float* base = V + (size_t)i0 * s0 + (size_t)j0 * s1
                              + (size_t)(k0 + kk) * N_FIELDS;

        float4 v00 = ld4(base);            // (i0, j0, k)
        float4 v01 = ld4(base + s1);       // (i0, j1, k)
        float4 v10 = ld4(base + s0);       // (i1, j0, k)
        float4 v11 = ld4(base + s0 + s1);  // (i1, j1, k)

        float4 a0 = lerp4(v00, v10, wx);
        float4 a1 = lerp4(v01, v11, wx);
        float4 b  = lerp4(a0, a1, wy);     // value at this lane's k corner

        float4 o;
        o.x = __shfl_xor_sync(0xffffffffu, b.x, 1);
        o.y = __shfl_xor_sync(0xffffffffu, b.y, 1);
        o.z = __shfl_xor_sync(0xffffffffu, b.z, 1);
        o.w = __shfl_xor_sync(0xffffffffu, b.w, 1);

        float4 lo = kk ? o : b;
        float4 hi = kk ? b : o;
        float4 c  = lerp4(lo, hi, wz);

        acc.x = fmaf(mult, c.x, acc.x);
        acc.y = fmaf(mult, c.y, acc.y);
        acc.z = fmaf(mult, c.z, acc.z);
        acc.w = fmaf(mult, c.w, acc.w);
    }

    // Scatter store to original index; lane pair splits the 16B into two
    // contiguous 8B halves.
    float2 half_val = kk ? make_float2(acc.z, acc.w) : make_float2(acc.x, acc.y);
    reinterpret_cast<float2*>(out)[2 * idx + kk] = half_val;
}

extern "C" void kernel_launch(void* const* d_in, const int* in_sizes, int n_in,
                              void* d_out, int out_size) {
    const float* x    = (const float*)d_in[0];
    const float* V16  = (const float*)d_in[1];
    const float* V32  = (const float*)d_in[2];
    const float* V64  = (const float*)d_in[3];
    const float* V128 = (const float*)d_in[4];
    float* out = (float*)d_out;

    int n = in_sizes[0] / 3;          // N_POINTS
    const int T = 256;

    zero_hist_kernel<<<(NBUCK + T - 1) / T, T>>>();
    hist_kernel<<<(n + T - 1) / T, T>>>(x, n);
    scan_kernel<<<1, 1024>>>();
    scatter_kernel<<<(n + T - 1) / T, T>>>(x, n);

    long long total = 2LL * n;        // 2 threads per point
    int blocks = (int)((total + T - 1) / T);
    composite_value_noise_kernel<<<blocks, T>>>(V16, V32, V64, V128, out, n);
}

// round 4
// speedup vs baseline: 4.6779x; 4.6779x over previous
#include <cuda_runtime.h>
#include <cuda_bf16.h>

// CompositeValueNoise, spatially-binned v2.
// R3's single-block scan was 32-way uncoalesced (~400us). Replaced with a
// coalesced 2-level scan; hist/scatter vectorized. Main kernel: 2 lanes per
// point on bin-sorted points so corner-load instructions touch few lines.

#define N_FIELDS 4
#define MAXN 2000000
#define BBITS 6
#define BDIM (1 << BBITS)            // 64
#define NBUCK (BDIM * BDIM * BDIM)   // 262144
#define SCAN_BLKS 256                // NBUCK / 1024

__device__ int    g_hist[NBUCK];
__device__ int    g_bsums[SCAN_BLKS];
__device__ float4 g_sorted[MAXN];

__device__ __forceinline__ int cell_key(float px, float py, float pz) {
    int ci = min(max((int)(px * (float)BDIM), 0), BDIM - 1);
    int cj = min(max((int)(py * (float)BDIM), 0), BDIM - 1);
    int ck = min(max((int)(pz * (float)BDIM), 0), BDIM - 1);
    return (ci << (2 * BBITS)) | (cj << BBITS) | ck;   // k innermost
}

__global__ void zero_hist_kernel() {
    int i = blockIdx.x * blockDim.x + threadIdx.x;
    if (i < NBUCK / 4)
        reinterpret_cast<int4*>(g_hist)[i] = make_int4(0, 0, 0, 0);
}

__global__ void hist_kernel(const float* __restrict__ x, int n) {
    int t = blockIdx.x * blockDim.x + threadIdx.x;
    int p0 = t * 4;
    if (p0 >= n) return;
    if (p0 + 4 <= n) {
        float4 a = __ldg(reinterpret_cast<const float4*>(x + 12 * (size_t)t));
        float4 b = __ldg(reinterpret_cast<const float4*>(x + 12 * (size_t)t + 4));
        float4 c = __ldg(reinterpret_cast<const float4*>(x + 12 * (size_t)t + 8));
        atomicAdd(&g_hist[cell_key(a.x, a.y, a.z)], 1);
        atomicAdd(&g_hist[cell_key(a.w, b.x, b.y)], 1);
        atomicAdd(&g_hist[cell_key(b.z, b.w, c.x)], 1);
        atomicAdd(&g_hist[cell_key(c.y, c.z, c.w)], 1);
    } else {
        for (int p = p0; p < n; ++p)
            atomicAdd(&g_hist[cell_key(x[3*p], x[3*p+1], x[3*p+2])], 1);
    }
}

// Level-1 scan: each of 256 blocks scans 1024 ints (coalesced int4), writes
// block-local exclusive prefixes in place and its total to g_bsums.
__global__ void scan1_kernel() {
    __shared__ int warp_sums[8];
    int b = blockIdx.x, t = threadIdx.x;
    int lane = t & 31, wid = t >> 5;
    int base = b * 1024 + t * 4;

    int4 v = *reinterpret_cast<int4*>(&g_hist[base]);
    int tot = v.x + v.y + v.z + v.w;

    int inc = tot;
    #pragma unroll
    for (int o = 1; o < 32; o <<= 1) {
        int u = __shfl_up_sync(0xffffffffu, inc, o);
        if (lane >= o) inc += u;
    }
    if (lane == 31) warp_sums[wid] = inc;
    __syncthreads();
    if (wid == 0 && lane < 8) {
        int w = warp_sums[lane];
        #pragma unroll
        for (int o = 1; o < 8; o <<= 1) {
            int u = __shfl_up_sync(0xffu, w, o);
            if (lane >= o) w += u;
        }
        warp_sums[lane] = w;
    }
    __syncthreads();
    int excl = (wid ? warp_sums[wid - 1] : 0) + inc - tot;

    int4 r;
    r.x = excl;
    r.y = excl + v.x;
    r.z = excl + v.x + v.y;
    r.w = excl + v.x + v.y + v.z;
    *reinterpret_cast<int4*>(&g_hist[base]) = r;
    if (t == 255) g_bsums[b] = excl + tot;
}

// Level-2: exclusive scan of the 256 block totals.
__global__ void scan2_kernel() {
    __shared__ int warp_sums[8];
    int t = threadIdx.x, lane = t & 31, wid = t >> 5;
    int v = g_bsums[t];
    int inc = v;
    #pragma unroll
    for (int o = 1; o < 32; o <<= 1) {
        int u = __shfl_up_sync(0xffffffffu, inc, o);
        if (lane >= o) inc += u;
    }
    if (lane == 31) warp_sums[wid] = inc;
    __syncthreads();
    if (wid == 0 && lane < 8) {
        int w = warp_sums[lane];
        #pragma unroll
        for (int o = 1; o < 8; o <<= 1) {
            int u = __shfl_up_sync(0xffu, w, o);
            if (lane >= o) w += u;
        }
        warp_sums[lane] = w;
    }
    __syncthreads();
    g_bsums[t] = (wid ? warp_sums[wid - 1] : 0) + inc - v;
}

__device__ __forceinline__ void scatter_one(float px, float py, float pz, int i) {
    int key = cell_key(px, py, pz);
    int pos = g_bsums[key >> 10] + atomicAdd(&g_hist[key], 1);
    g_sorted[pos] = make_float4(px, py, pz, __int_as_float(i));
}

__global__ void scatter_kernel(const float* __restrict__ x, int n) {
    int t = blockIdx.x * blockDim.x + threadIdx.x;
    int p0 = t * 4;
    if (p0 >= n) return;
    if (p0 + 4 <= n) {
        float4 a = __ldg(reinterpret_cast<const float4*>(x + 12 * (size_t)t));
        float4 b = __ldg(reinterpret_cast<const float4*>(x + 12 * (size_t)t + 4));
        float4 c = __ldg(reinterpret_cast<const float4*>(x + 12 * (size_t)t + 8));
        scatter_one(a.x, a.y, a.z, p0 + 0);
        scatter_one(a.w, b.x, b.y, p0 + 1);
        scatter_one(b.z, b.w, c.x, p0 + 2);
        scatter_one(c.y, c.z, c.w, p0 + 3);
    } else {
        for (int p = p0; p < n; ++p)
            scatter_one(x[3*p], x[3*p+1], x[3*p+2], p);
    }
}

__device__ __forceinline__ float4 ld4(const float* __restrict__ p) {
    return __ldg(reinterpret_cast<const float4*>(p));
}

__device__ __forceinline__ float4 lerp4(float4 a, float4 b, float w) {
    float4 r;
    r.x = fmaf(w, b.x - a.x, a.x);
    r.y = fmaf(w, b.y - a.y, a.y);
    r.z = fmaf(w, b.z - a.z, a.z);
    r.w = fmaf(w, b.w - a.w, a.w);
    return r;
}

__global__ void __launch_bounds__(256) composite_value_noise_kernel(
    const float* __restrict__ V16,
    const float* __restrict__ V32,
    const float* __restrict__ V64,
    const float* __restrict__ V128,
    float* __restrict__ out,
    int n)
{
    int gtid = blockIdx.x * blockDim.x + threadIdx.x;
    int p  = gtid >> 1;
    int kk = gtid & 1;
    if (p >= n) return;

    float4 pt = g_sorted[p];
    const float px = pt.x, py = pt.y, pz = pt.z;
    const int   idx = __float_as_int(pt.w);

    const float* grids[4] = {V16, V32, V64, V128};
    const int    ress[4]  = {16, 32, 64, 128};

    float4 acc = make_float4(0.f, 0.f, 0.f, 0.f);

    #pragma unroll
    for (int L = 0; L < 4; ++L) {
        const float* __restrict__ V = grids[L];
        const int   res  = ress[L];
        const float resf = (float)res;
        const float mult = 16.0f / resf;

        // x in [0,1) -> x*res < res, fmod is identity
        float xs = px * resf, ys = py * resf, zs = pz * resf;

        float fx = floorf(xs), fy = floorf(ys), fz = floorf(zs);
        float tx = xs - fx,    ty = ys - fy,    tz = zs - fz;

        int i0 = (int)fx, j0 = (int)fy, k0 = (int)fz;

        float wx = (3.0f - 2.0f * tx) * tx * tx;
        float wy = (3.0f - 2.0f * ty) * ty * ty;
        float wz = (3.0f - 2.0f * tz) * tz * tz;

        const int r1 = res + 1;
        const int s1 = r1 * N_FIELDS;
        const int s0 = r1 * s1;

        const float* base = V + (size_t)i0 * s0 + (size_t)j0 * s1
                              + (size_t)(k0 + kk) * N_FIELDS;

        float4 v00 = ld4(base);
        float4 v01 = ld4(base + s1);
        float4 v10 = ld4(base + s0);
        float4 v11 = ld4(base + s0 + s1);

        float4 a0 = lerp4(v00, v10, wx);
        float4 a1 = lerp4(v01, v11, wx);
        float4 b  = lerp4(a0, a1, wy);

        float4 o;
        o.x = __shfl_xor_sync(0xffffffffu, b.x, 1);
        o.y = __shfl_xor_sync(0xffffffffu, b.y, 1);
        o.z = __shfl_xor_sync(0xffffffffu, b.z, 1);
        o.w = __shfl_xor_sync(0xffffffffu, b.w, 1);

        float4 lo = kk ? o : b;
        float4 hi = kk ? b : o;
        float4 c  = lerp4(lo, hi, wz);

        acc.x = fmaf(mult, c.x, acc.x);
        acc.y = fmaf(mult, c.y, acc.y);
        acc.z = fmaf(mult, c.z, acc.z);
        acc.w = fmaf(mult, c.w, acc.w);
    }

    float2 half_val = kk ? make_float2(acc.z, acc.w) : make_float2(acc.x, acc.y);
    reinterpret_cast<float2*>(out)[2 * (size_t)idx + kk] = half_val;
}

extern "C" void kernel_launch(void* const* d_in, const int* in_sizes, int n_in,
                              void* d_out, int out_size) {
    const float* x    = (const float*)d_in[0];
    const float* V16  = (const float*)d_in[1];
    const float* V32  = (const float*)d_in[2];
    const float* V64  = (const float*)d_in[3];
    const float* V128 = (const float*)d_in[4];
    float* out = (float*)d_out;

    int n = in_sizes[0] / 3;
    const int T = 256;
    int nquads = (n + 3) / 4;

    zero_hist_kernel<<<(NBUCK / 4 + T - 1) / T, T>>>();
    hist_kernel<<<(nquads + T - 1) / T, T>>>(x, n);
    scan1_kernel<<<SCAN_BLKS, 256>>>();
    scan2_kernel<<<1, 256>>>();
    scatter_kernel<<<(nquads + T - 1) / T, T>>>(x, n);

    long long total = 2LL * n;
    int blocks = (int)((total + T - 1) / T);
    composite_value_noise_kernel<<<blocks, T>>>(V16, V32, V64, V128, out, n);
}

// round 5
// speedup vs baseline: 4.8080x; 1.0278x over previous
#include <cuda_runtime.h>
#include <cuda_bf16.h>

// CompositeValueNoise, spatially-binned v3.
// Changes vs R4: (1) scan2 kernel eliminated — scan1 blocks take their global
// base via one atomicAdd (segment order run-varying; output values and
// destinations unchanged -> bit-deterministic out). (2) BBITS 6->7: bins at
// V128 cell resolution (~1 pt/bucket) so the main kernel's V128/V64 corner
// loads touch ~3x fewer cache lines per warp.

#define N_FIELDS 4
#define MAXN 2000000
#define BBITS 7
#define BDIM (1 << BBITS)            // 128
#define NBUCK (BDIM * BDIM * BDIM)   // 2097152
#define SCAN_BLKS (NBUCK / 1024)     // 2048

__device__ int    g_hist[NBUCK];
__device__ int    g_bsums[SCAN_BLKS];
__device__ int    g_counter;
__device__ float4 g_sorted[MAXN];

__device__ __forceinline__ int cell_key(float px, float py, float pz) {
    int ci = min(max((int)(px * (float)BDIM), 0), BDIM - 1);
    int cj = min(max((int)(py * (float)BDIM), 0), BDIM - 1);
    int ck = min(max((int)(pz * (float)BDIM), 0), BDIM - 1);
    return (ci << (2 * BBITS)) | (cj << BBITS) | ck;   // k innermost
}

__global__ void zero_hist_kernel() {
    int i = blockIdx.x * blockDim.x + threadIdx.x;
    if (i < NBUCK / 4)
        reinterpret_cast<int4*>(g_hist)[i] = make_int4(0, 0, 0, 0);
    if (i == 0) g_counter = 0;
}

__global__ void hist_kernel(const float* __restrict__ x, int n) {
    int t = blockIdx.x * blockDim.x + threadIdx.x;
    int p0 = t * 4;
    if (p0 >= n) return;
    if (p0 + 4 <= n) {
        float4 a = __ldg(reinterpret_cast<const float4*>(x + 12 * (size_t)t));
        float4 b = __ldg(reinterpret_cast<const float4*>(x + 12 * (size_t)t + 4));
        float4 c = __ldg(reinterpret_cast<const float4*>(x + 12 * (size_t)t + 8));
        atomicAdd(&g_hist[cell_key(a.x, a.y, a.z)], 1);
        atomicAdd(&g_hist[cell_key(a.w, b.x, b.y)], 1);
        atomicAdd(&g_hist[cell_key(b.z, b.w, c.x)], 1);
        atomicAdd(&g_hist[cell_key(c.y, c.z, c.w)], 1);
    } else {
        for (int p = p0; p < n; ++p)
            atomicAdd(&g_hist[cell_key(x[3*p], x[3*p+1], x[3*p+2])], 1);
    }
}

// Each of SCAN_BLKS blocks scans 1024 ints (coalesced int4) into block-local
// exclusive prefixes in place, then grabs its global segment base via one
// atomicAdd on g_counter (segment order is arbitrary; only contiguity of each
// bucket and of each 1024-key neighborhood matters for locality).
__global__ void scan1_kernel() {
    __shared__ int warp_sums[8];
    int b = blockIdx.x, t = threadIdx.x;
    int lane = t & 31, wid = t >> 5;
    int base = b * 1024 + t * 4;

    int4 v = *reinterpret_cast<int4*>(&g_hist[base]);
    int tot = v.x + v.y + v.z + v.w;

    int inc = tot;
    #pragma unroll
    for (int o = 1; o < 32; o <<= 1) {
        int u = __shfl_up_sync(0xffffffffu, inc, o);
        if (lane >= o) inc += u;
    }
    if (lane == 31) warp_sums[wid] = inc;
    __syncthreads();
    if (wid == 0 && lane < 8) {
        int w = warp_sums[lane];
        #pragma unroll
        for (int o = 1; o < 8; o <<= 1) {
            int u = __shfl_up_sync(0xffu, w, o);
            if (lane >= o) w += u;
        }
        warp_sums[lane] = w;
    }
    __syncthreads();
    int excl = (wid ? warp_sums[wid - 1] : 0) + inc - tot;

    int4 r;
    r.x = excl;
    r.y = excl + v.x;
    r.z = excl + v.x + v.y;
    r.w = excl + v.x + v.y + v.z;
    *reinterpret_cast<int4*>(&g_hist[base]) = r;

    if (t == 255)
        g_bsums[b] = atomicAdd(&g_counter, excl + tot);
}

__device__ __forceinline__ void scatter_one(float px, float py, float pz, int i) {
    int key = cell_key(px, py, pz);
    int pos = g_bsums[key >> 10] + atomicAdd(&g_hist[key], 1);
    g_sorted[pos] = make_float4(px, py, pz, __int_as_float(i));
}

__global__ void scatter_kernel(const float* __restrict__ x, int n) {
    int t = blockIdx.x * blockDim.x + threadIdx.x;
    int p0 = t * 4;
    if (p0 >= n) return;
    if (p0 + 4 <= n) {
        float4 a = __ldg(reinterpret_cast<const float4*>(x + 12 * (size_t)t));
        float4 b = __ldg(reinterpret_cast<const float4*>(x + 12 * (size_t)t + 4));
        float4 c = __ldg(reinterpret_cast<const float4*>(x + 12 * (size_t)t + 8));
        scatter_one(a.x, a.y, a.z, p0 + 0);
        scatter_one(a.w, b.x, b.y, p0 + 1);
        scatter_one(b.z, b.w, c.x, p0 + 2);
        scatter_one(c.y, c.z, c.w, p0 + 3);
    } else {
        for (int p = p0; p < n; ++p)
            scatter_one(x[3*p], x[3*p+1], x[3*p+2], p);
    }
}

__device__ __forceinline__ float4 ld4(const float* __restrict__ p) {
    return __ldg(reinterpret_cast<const float4*>(p));
}

__device__ __forceinline__ float4 lerp4(float4 a, float4 b, float w) {
    float4 r;
    r.x = fmaf(w, b.x - a.x, a.x);
    r.y = fmaf(w, b.y - a.y, a.y);
    r.z = fmaf(w, b.z - a.z, a.z);
    r.w = fmaf(w, b.w - a.w, a.w);
    return r;
}

__global__ void __launch_bounds__(256) composite_value_noise_kernel(
    const float* __restrict__ V16,
    const float* __restrict__ V32,
    const float* __restrict__ V64,
    const float* __restrict__ V128,
    float* __restrict__ out,
    int n)
{
    int gtid = blockIdx.x * blockDim.x + threadIdx.x;
    int p  = gtid >> 1;
    int kk = gtid & 1;
    if (p >= n) return;

    float4 pt = g_sorted[p];
    const float px = pt.x, py = pt.y, pz = pt.z;
    const int   idx = __float_as_int(pt.w);

    const float* grids[4] = {V16, V32, V64, V128};
    const int    ress[4]  = {16, 32, 64, 128};

    float4 acc = make_float4(0.f, 0.f, 0.f, 0.f);

    #pragma unroll
    for (int L = 0; L < 4; ++L) {
        const float* __restrict__ V = grids[L];
        const int   res  = ress[L];
        const float resf = (float)res;
        const float mult = 16.0f / resf;

        // x in [0,1) -> x*res < res, fmod is identity
        float xs = px * resf, ys = py * resf, zs = pz * resf;

        float fx = floorf(xs), fy = floorf(ys), fz = floorf(zs);
        float tx = xs - fx,    ty = ys - fy,    tz = zs - fz;

        int i0 = (int)fx, j0 = (int)fy, k0 = (int)fz;

        float wx = (3.0f - 2.0f * tx) * tx * tx;
        float wy = (3.0f - 2.0f * ty) * ty * ty;
        float wz = (3.0f - 2.0f * tz) * tz * tz;

        const int r1 = res + 1;
        const int s1 = r1 * N_FIELDS;
        const int s0 = r1 * s1;

        const float* base = V + (size_t)i0 * s0 + (size_t)j0 * s1
                              + (size_t)(k0 + kk) * N_FIELDS;

        float4 v00 = ld4(base);
        float4 v01 = ld4(base + s1);
        float4 v10 = ld4(base + s0);
        float4 v11 = ld4(base + s0 + s1);

        float4 a0 = lerp4(v00, v10, wx);
        float4 a1 = lerp4(v01, v11, wx);
        float4 b  = lerp4(a0, a1, wy);

        float4 o;
        o.x = __shfl_xor_sync(0xffffffffu, b.x, 1);
        o.y = __shfl_xor_sync(0xffffffffu, b.y, 1);
        o.z = __shfl_xor_sync(0xffffffffu, b.z, 1);
        o.w = __shfl_xor_sync(0xffffffffu, b.w, 1);

        float4 lo = kk ? o : b;
        float4 hi = kk ? b : o;
        float4 c  = lerp4(lo, hi, wz);

        acc.x = fmaf(mult, c.x, acc.x);
        acc.y = fmaf(mult, c.y, acc.y);
        acc.z = fmaf(mult, c.z, acc.z);
        acc.w = fmaf(mult, c.w, acc.w);
    }

    float2 half_val = kk ? make_float2(acc.z, acc.w) : make_float2(acc.x, acc.y);
    reinterpret_cast<float2*>(out)[2 * (size_t)idx + kk] = half_val;
}

extern "C" void kernel_launch(void* const* d_in, const int* in_sizes, int n_in,
                              void* d_out, int out_size) {
    const float* x    = (const float*)d_in[0];
    const float* V16  = (const float*)d_in[1];
    const float* V32  = (const float*)d_in[2];
    const float* V64  = (const float*)d_in[3];
    const float* V128 = (const float*)d_in[4];
    float* out = (float*)d_out;

    int n = in_sizes[0] / 3;
    const int T = 256;
    int nquads = (n + 3) / 4;

    zero_hist_kernel<<<(NBUCK / 4 + T - 1) / T, T>>>();
    hist_kernel<<<(nquads + T - 1) / T, T>>>(x, n);
    scan1_kernel<<<SCAN_BLKS, 256>>>();
    scatter_kernel<<<(nquads + T - 1) / T, T>>>(x, n);

    long long total = 2LL * n;
    int blocks = (int)((total + T - 1) / T);
    composite_value_noise_kernel<<<blocks, T>>>(V16, V32, V64, V128, out, n);
}